// round 1
// baseline (speedup 1.0000x reference)
#include <cuda_runtime.h>

#define Nn 65536
#define Ee 2097152
#define Bb 1024
#define FXDIM 78
#define DIM 32
#define EMBD 128
#define VOCAB 26
#define PLENN 1000
#define KSZ 8
#define CLENN 121
#define NFIL 32
#define ADIM 6656   /* VOCAB * NFIL * KSZ */
#define OUTDIM 128

// ---------------- scratch (device globals; no allocations) ----------------
__device__ float g_p[Nn * DIM];
__device__ float g_agg[Nn * DIM];
__device__ float g_y[Nn * DIM];
__device__ float g_stats[64];
__device__ float g_sb[64];          // s[32], t[32] (BN affine fold)
__device__ float g_hg[Bb * DIM];
__device__ float g_xc[Bb * 256];    // [xd | xt]
__device__ float g_f1[Bb * 1024];
__device__ float g_f2[Bb * 256];
__device__ float g_Wt[PLENN * 256]; // conv_w transposed to [p][f*8+k]
__device__ float g_A[Bb * ADIM];
__device__ float g_U[ADIM * OUTDIM];
__device__ float g_bias2[OUTDIM];

// ---------------- small init ----------------
__global__ void k_init() {
    int i = blockIdx.x * 256 + threadIdx.x;
    if (i < Bb * DIM) g_hg[i] = 0.f;
    if (i < OUTDIM) g_bias2[i] = 0.f;
}

// ---------------- protein branch ----------------
__global__ void k_transpose(const float* __restrict__ conv_w) {
    int f = blockIdx.x;
    for (int i = threadIdx.x; i < PLENN * KSZ; i += 256) {
        int p = i >> 3, k = i & 7;
        g_Wt[p * 256 + f * 8 + k] = conv_w[f * PLENN * KSZ + i];
    }
}

__global__ void k_buildA(const int* __restrict__ target) {
    __shared__ float sA[ADIM];
    int b = blockIdx.x, tid = threadIdx.x;
    for (int i = tid; i < ADIM; i += 256) sA[i] = 0.f;
    __syncthreads();
    const int* tb = target + b * PLENN;
    for (int p = 0; p < PLENN; p += 4) {
        int v0 = tb[p], v1 = tb[p + 1], v2 = tb[p + 2], v3 = tb[p + 3];
        float w0 = g_Wt[(p + 0) * 256 + tid];
        float w1 = g_Wt[(p + 1) * 256 + tid];
        float w2 = g_Wt[(p + 2) * 256 + tid];
        float w3 = g_Wt[(p + 3) * 256 + tid];
        sA[v0 * 256 + tid] += w0;
        sA[v1 * 256 + tid] += w1;
        sA[v2 * 256 + tid] += w2;
        sA[v3 * 256 + tid] += w3;
    }
    __syncthreads();
    for (int i = tid; i < ADIM; i += 256) g_A[b * ADIM + i] = sA[i];
}

// U[(v*256+f*8+k)*128+o] = sum_t emb[v*128+t+k] * w_fcxt[(f*121+t)*128+o]
__global__ void k_buildU(const float* __restrict__ emb, const float* __restrict__ wfcxt) {
    __shared__ float se[VOCAB * EMBD];
    int f = blockIdx.x, ch = blockIdx.y, o = threadIdx.x; // 128 threads
    for (int i = o; i < VOCAB * EMBD; i += 128) se[i] = emb[i];
    __syncthreads();
    float acc[26];
    int base[26];
#pragma unroll
    for (int j = 0; j < 26; j++) {
        acc[j] = 0.f;
        int vk = ch * 26 + j;
        base[j] = (vk >> 3) * EMBD + (vk & 7);
    }
    const float* wf = wfcxt + f * CLENN * OUTDIM + o;
    for (int t = 0; t < CLENN; t++) {
        float wv = wf[t * OUTDIM];
#pragma unroll
        for (int j = 0; j < 26; j++) acc[j] += se[base[j] + t] * wv;
    }
#pragma unroll
    for (int j = 0; j < 26; j++) {
        int vk = ch * 26 + j;
        int v = vk >> 3, k = vk & 7;
        g_U[(v * 256 + f * 8 + k) * OUTDIM + o] = acc[j];
    }
}

__global__ void k_bias2(const float* __restrict__ wfcxt, const float* __restrict__ conv_b) {
    int f = blockIdx.x, o = threadIdx.x; // 128 threads
    float s = 0.f;
    for (int t = 0; t < CLENN; t++) s += wfcxt[(f * CLENN + t) * OUTDIM + o];
    atomicAdd(&g_bias2[o], s * conv_b[f]);
}

__global__ void k_xtinit(const float* __restrict__ b_fcxt) {
    g_xc[blockIdx.x * 256 + 128 + threadIdx.x] = g_bias2[threadIdx.x] + b_fcxt[threadIdx.x];
}

__global__ void k_f2init(const float* __restrict__ b_fc2) {
    g_f2[blockIdx.x * 256 + threadIdx.x] = b_fc2[threadIdx.x];
}

// ---------------- GIN layers ----------------
// layer 1 projection: p = x @ w1a   (x: [N,78], w1a: [78,32])
__global__ void k_proj78(const float* __restrict__ x, const float* __restrict__ W) {
    __shared__ float xs[64][80];
    __shared__ float ws[78][33];
    int tid = threadIdx.x;
    int row0 = blockIdx.x * 64;
    const float* xb = x + row0 * FXDIM;
    for (int i = tid; i < 64 * FXDIM; i += 256) xs[i / FXDIM][i % FXDIM] = xb[i];
    for (int i = tid; i < FXDIM * 32; i += 256) ws[i >> 5][i & 31] = W[i];
    __syncthreads();
    int c = tid & 31, w = tid >> 5;
    float acc[8];
#pragma unroll
    for (int j = 0; j < 8; j++) acc[j] = 0.f;
    for (int k = 0; k < FXDIM; k++) {
        float wv = ws[k][c];
#pragma unroll
        for (int j = 0; j < 8; j++) acc[j] += xs[w * 8 + j][k] * wv;
    }
#pragma unroll
    for (int j = 0; j < 8; j++) {
        int idx = (row0 + w * 8 + j) * 32 + c;
        g_p[idx] = acc[j];
        g_agg[idx] = acc[j];
    }
}

// layers 2-5 projection with folded BN affine: p = (y*s+t) @ W
__global__ void k_proj32(const float* __restrict__ W) {
    __shared__ float xs[64][33];
    __shared__ float ws[32][33];
    __shared__ float sa[64];
    int tid = threadIdx.x;
    int row0 = blockIdx.x * 64;
    if (tid < 64) sa[tid] = g_sb[tid];
    __syncthreads();
    for (int i = tid; i < 2048; i += 256) {
        int r = i >> 5, k = i & 31;
        xs[r][k] = g_y[(row0 + r) * 32 + k] * sa[k] + sa[32 + k];
    }
    for (int i = tid; i < 1024; i += 256) ws[i >> 5][i & 31] = W[i];
    __syncthreads();
    int c = tid & 31, w = tid >> 5;
    float acc[8];
#pragma unroll
    for (int j = 0; j < 8; j++) acc[j] = 0.f;
#pragma unroll
    for (int k = 0; k < 32; k++) {
        float wv = ws[k][c];
#pragma unroll
        for (int j = 0; j < 8; j++) acc[j] += xs[w * 8 + j][k] * wv;
    }
#pragma unroll
    for (int j = 0; j < 8; j++) {
        int idx = (row0 + w * 8 + j) * 32 + c;
        g_p[idx] = acc[j];
        g_agg[idx] = acc[j];
    }
}

// edge scatter: agg[dst] += p[src]; warp per edge. Also zeroes BN stats.
__global__ void k_scatter(const int* __restrict__ ei) {
    if (blockIdx.x == 0 && threadIdx.x < 64) g_stats[threadIdx.x] = 0.f;
    int gid = blockIdx.x * 256 + threadIdx.x;
    int e = gid >> 5, d = gid & 31;
    if (e < Ee) {
        int s = ei[e];
        int t = ei[Ee + e];
        atomicAdd(&g_agg[t * 32 + d], g_p[s * 32 + d]);
    }
}

// y = relu(relu(agg + ba) @ Wb + bb), accumulate per-channel sum/sumsq
__global__ void k_mlp(const float* __restrict__ ba, const float* __restrict__ Wb,
                      const float* __restrict__ bb) {
    __shared__ float us[64][33];
    __shared__ float ws[32][33];
    __shared__ float r1[8][32];
    __shared__ float r2[8][32];
    __shared__ float bsh[32], bbsh[32];
    int tid = threadIdx.x;
    int row0 = blockIdx.x * 64;
    if (tid < 32) { bsh[tid] = ba[tid]; bbsh[tid] = bb[tid]; }
    __syncthreads();
    for (int i = tid; i < 2048; i += 256) {
        int r = i >> 5, k = i & 31;
        us[r][k] = fmaxf(g_agg[(row0 + r) * 32 + k] + bsh[k], 0.f);
    }
    for (int i = tid; i < 1024; i += 256) ws[i >> 5][i & 31] = Wb[i];
    __syncthreads();
    int c = tid & 31, w = tid >> 5;
    float acc[8];
#pragma unroll
    for (int j = 0; j < 8; j++) acc[j] = bbsh[c];
#pragma unroll
    for (int k = 0; k < 32; k++) {
        float wv = ws[k][c];
#pragma unroll
        for (int j = 0; j < 8; j++) acc[j] += us[w * 8 + j][k] * wv;
    }
    float s1 = 0.f, s2 = 0.f;
#pragma unroll
    for (int j = 0; j < 8; j++) {
        float v = fmaxf(acc[j], 0.f);
        g_y[(row0 + w * 8 + j) * 32 + c] = v;
        s1 += v;
        s2 += v * v;
    }
    r1[w][c] = s1;
    r2[w][c] = s2;
    __syncthreads();
    if (w == 0) {
        float a = 0.f, b2 = 0.f;
#pragma unroll
        for (int q = 0; q < 8; q++) { a += r1[q][c]; b2 += r2[q][c]; }
        atomicAdd(&g_stats[c], a);
        atomicAdd(&g_stats[32 + c], b2);
    }
}

__global__ void k_bnstats(const float* __restrict__ gamma, const float* __restrict__ beta) {
    int c = threadIdx.x; // 32 threads
    float m = g_stats[c] * (1.f / Nn);
    float v = g_stats[32 + c] * (1.f / Nn) - m * m;
    float s = gamma[c] * rsqrtf(v + 1e-5f);
    g_sb[c] = s;
    g_sb[32 + c] = beta[c] - m * s;
}

// global add pool with BN affine applied on the fly
__global__ void k_pool(const int* __restrict__ batch) {
    int gid = blockIdx.x * 256 + threadIdx.x;
    int n = gid >> 5, d = gid & 31;
    if (n < Nn) {
        float v = g_y[n * 32 + d] * g_sb[d] + g_sb[32 + d];
        atomicAdd(&g_hg[batch[n] * 32 + d], v);
    }
}

// ---------------- generic fp32 GEMM: C[M,N] (+)= A[M,K] @ W[K,N] ----------------
// block tile 64x128, thread tile 8x4, 256 threads. N = gridDim.y*128. K % 16 == 0.
template <bool RELU, bool ATOMIC>
__global__ void gemm64x128(const float* __restrict__ A, const float* __restrict__ W,
                           const float* __restrict__ bias, float* __restrict__ C,
                           int K, int ldc, int kChunk) {
    const int N = gridDim.y * 128;
    __shared__ float As[64][16];
    __shared__ float Ws[16][128];
    int tid = threadIdx.x;
    int tx = tid & 31, ty = tid >> 5;
    int row0 = blockIdx.x * 64;
    int col0 = blockIdx.y * 128;
    int k0 = blockIdx.z * kChunk;
    int k1 = k0 + kChunk;
    if (k1 > K) k1 = K;
    float acc[8][4];
#pragma unroll
    for (int i = 0; i < 8; i++)
#pragma unroll
        for (int m = 0; m < 4; m++) acc[i][m] = 0.f;
    int arow = tid >> 2, ak = (tid & 3) * 4;
    int wk = tid >> 4, wc = (tid & 15) * 8;
    for (int kb = k0; kb < k1; kb += 16) {
        float4 av = *(const float4*)(A + (row0 + arow) * K + kb + ak);
        *(float4*)(&As[arow][ak]) = av;
        float4 w0 = *(const float4*)(W + (kb + wk) * N + col0 + wc);
        float4 w1 = *(const float4*)(W + (kb + wk) * N + col0 + wc + 4);
        *(float4*)(&Ws[wk][wc]) = w0;
        *(float4*)(&Ws[wk][wc + 4]) = w1;
        __syncthreads();
#pragma unroll
        for (int kk = 0; kk < 16; kk++) {
            float rw[4];
#pragma unroll
            for (int m = 0; m < 4; m++) rw[m] = Ws[kk][tx + 32 * m];
#pragma unroll
            for (int i = 0; i < 8; i++) {
                float ra = As[ty * 8 + i][kk];
#pragma unroll
                for (int m = 0; m < 4; m++) acc[i][m] += ra * rw[m];
            }
        }
        __syncthreads();
    }
#pragma unroll
    for (int i = 0; i < 8; i++) {
        int r = row0 + ty * 8 + i;
#pragma unroll
        for (int m = 0; m < 4; m++) {
            int c = col0 + tx + 32 * m;
            if (ATOMIC) {
                atomicAdd(&C[r * ldc + c], acc[i][m]);
            } else {
                float v = acc[i][m] + (bias ? bias[c] : 0.f);
                if (RELU) v = fmaxf(v, 0.f);
                C[r * ldc + c] = v;
            }
        }
    }
}

// ---------------- final head ----------------
__global__ void k_out(const float* __restrict__ wout, const float* __restrict__ bout,
                      float* __restrict__ out) {
    int b = blockIdx.x, c = threadIdx.x; // 256 threads
    float v = fmaxf(g_f2[b * 256 + c], 0.f) * wout[c];
#pragma unroll
    for (int off = 16; off; off >>= 1) v += __shfl_down_sync(0xffffffffu, v, off);
    __shared__ float ps[8];
    if ((c & 31) == 0) ps[c >> 5] = v;
    __syncthreads();
    if (c == 0) {
        float t = bout[0];
#pragma unroll
        for (int q = 0; q < 8; q++) t += ps[q];
        out[b] = t;
    }
}

// ---------------- launcher ----------------
extern "C" void kernel_launch(void* const* d_in, const int* in_sizes, int n_in,
                              void* d_out, int out_size) {
    const float* x = (const float*)d_in[0];
    const int* edge_index = (const int*)d_in[1];
    const int* batch = (const int*)d_in[2];
    const int* target = (const int*)d_in[3];
    const float* w1a = (const float*)d_in[4];
    const float* b1a = (const float*)d_in[5];
    const float* w1b = (const float*)d_in[6];
    const float* b1b = (const float*)d_in[7];
    const float* wa = (const float*)d_in[8];
    const float* ba = (const float*)d_in[9];
    const float* wb = (const float*)d_in[10];
    const float* bb = (const float*)d_in[11];
    const float* gamma = (const float*)d_in[12];
    const float* beta = (const float*)d_in[13];
    const float* w_fcxd = (const float*)d_in[14];
    const float* b_fcxd = (const float*)d_in[15];
    const float* emb = (const float*)d_in[16];
    const float* conv_w = (const float*)d_in[17];
    const float* conv_b = (const float*)d_in[18];
    const float* w_fcxt = (const float*)d_in[19];
    const float* b_fcxt = (const float*)d_in[20];
    const float* w_fc1 = (const float*)d_in[21];
    const float* b_fc1 = (const float*)d_in[22];
    const float* w_fc2 = (const float*)d_in[23];
    const float* b_fc2 = (const float*)d_in[24];
    const float* w_out = (const float*)d_in[25];
    const float* b_out = (const float*)d_in[26];
    float* out = (float*)d_out;

    // resolve scratch addresses for GEMM arguments
    float *hgP, *xcP, *f1P, *f2P, *AP, *UP;
    cudaGetSymbolAddress((void**)&hgP, g_hg);
    cudaGetSymbolAddress((void**)&xcP, g_xc);
    cudaGetSymbolAddress((void**)&f1P, g_f1);
    cudaGetSymbolAddress((void**)&f2P, g_f2);
    cudaGetSymbolAddress((void**)&AP, g_A);
    cudaGetSymbolAddress((void**)&UP, g_U);

    k_init<<<129, 256>>>();

    // protein branch
    k_transpose<<<NFIL, 256>>>(conv_w);
    k_buildA<<<Bb, 256>>>(target);
    k_buildU<<<dim3(NFIL, 8), 128>>>(emb, w_fcxt);
    k_bias2<<<NFIL, 128>>>(w_fcxt, conv_b);
    k_xtinit<<<Bb, 128>>>(b_fcxt);
    k_f2init<<<Bb, 256>>>(b_fc2);

    // GIN layer 1
    k_proj78<<<Nn / 64, 256>>>(x, w1a);
    k_scatter<<<(Ee * 32) / 256, 256>>>(edge_index);
    k_mlp<<<Nn / 64, 256>>>(b1a, w1b, b1b);
    k_bnstats<<<1, 32>>>(gamma, beta);

    // GIN layers 2-5
    for (int l = 0; l < 4; l++) {
        k_proj32<<<Nn / 64, 256>>>(wa + l * 1024);
        k_scatter<<<(Ee * 32) / 256, 256>>>(edge_index);
        k_mlp<<<Nn / 64, 256>>>(ba + l * 32, wb + l * 1024, bb + l * 32);
        k_bnstats<<<1, 32>>>(gamma + (l + 1) * 32, beta + (l + 1) * 32);
    }

    // pool + drug head  (xd -> g_xc[:, 0:128])
    k_pool<<<(Nn * 32) / 256, 256>>>(batch);
    gemm64x128<true, false><<<dim3(16, 1, 1), 256>>>(hgP, w_fcxd, b_fcxd, xcP, 32, 256, 32);

    // protein head (xt -> g_xc[:, 128:256], atomic split-K onto bias-initialized region)
    gemm64x128<false, true><<<dim3(16, 1, 8), 256>>>(AP, UP, nullptr, xcP + 128, ADIM, 256, 832);

    // joint head
    gemm64x128<true, false><<<dim3(16, 8, 1), 256>>>(xcP, w_fc1, b_fc1, f1P, 256, 1024, 256);
    gemm64x128<false, true><<<dim3(16, 2, 4), 256>>>(f1P, w_fc2, nullptr, f2P, 1024, 256, 256);
    k_out<<<Bb, 256>>>(w_out, b_out, out);
}

// round 2
// speedup vs baseline: 1.5087x; 1.5087x over previous
#include <cuda_runtime.h>

#define Nn 65536
#define Ee 2097152
#define Bb 1024
#define FXDIM 78
#define DIM 32
#define EMBD 128
#define VOCAB 26
#define PLENN 1000
#define KSZ 8
#define CLENN 121
#define NFIL 32
#define ADIM 6656   /* VOCAB * NFIL * KSZ */
#define OUTDIM 128

// ---------------- scratch (device globals; no allocations) ----------------
__device__ float g_p[Nn * DIM];
__device__ float g_y[Nn * DIM];
__device__ float g_stats[64];
__device__ float g_sb[64];          // s[32], t[32] (BN affine fold)
__device__ float g_hg[Bb * DIM];
__device__ float g_xc[Bb * 256];    // [xd | xt]
__device__ float g_f1[Bb * 1024];
__device__ float g_f2[Bb * 256];
__device__ float g_Wt[PLENN * 256]; // conv_w transposed to [p][f*8+k]
__device__ float g_A[Bb * ADIM];
__device__ float g_U[ADIM * OUTDIM];
__device__ float g_bias2[OUTDIM];
// CSR scratch
__device__ int g_off[Nn + 1];
__device__ int g_pos[Nn];
__device__ int g_srcl[Ee];

// ---------------- init ----------------
__global__ void k_init() {
    int i = blockIdx.x * 256 + threadIdx.x;   // 65536 threads
    if (i < Nn) g_pos[i] = 0;                 // degree counters
    if (i < Bb * DIM) g_hg[i] = 0.f;
    if (i < 64) g_stats[i] = 0.f;
    if (i < OUTDIM) g_bias2[i] = 0.f;
}

// ---------------- CSR build ----------------
__global__ void k_hist(const int* __restrict__ ei) {
    int e = blockIdx.x * 256 + threadIdx.x;
    atomicAdd(&g_pos[ei[Ee + e]], 1);
}

__global__ void k_scan() {  // 1 block, 1024 threads, 64 elems each
    int t = threadIdx.x, lane = t & 31, wid = t >> 5;
    __shared__ int ws[32];
    int base = t * 64;
    int s = 0;
    for (int j = 0; j < 64; j++) s += g_pos[base + j];
    int v = s;
#pragma unroll
    for (int off = 1; off < 32; off <<= 1) {
        int u = __shfl_up_sync(0xffffffffu, v, off);
        if (lane >= off) v += u;
    }
    if (lane == 31) ws[wid] = v;
    __syncthreads();
    if (wid == 0) {
        int w = ws[lane];
#pragma unroll
        for (int off = 1; off < 32; off <<= 1) {
            int u = __shfl_up_sync(0xffffffffu, w, off);
            if (lane >= off) w += u;
        }
        ws[lane] = w;
    }
    __syncthreads();
    int run = v - s + (wid ? ws[wid - 1] : 0);
    for (int j = 0; j < 64; j++) {
        int d = g_pos[base + j];
        g_off[base + j] = run;
        g_pos[base + j] = run;
        run += d;
    }
    if (t == 1023) g_off[Nn] = run;
}

__global__ void k_fill(const int* __restrict__ ei) {
    int e = blockIdx.x * 256 + threadIdx.x;
    int d = ei[Ee + e];
    int slot = atomicAdd(&g_pos[d], 1);
    g_srcl[slot] = ei[e];
}

// ---------------- protein branch ----------------
__global__ void k_transpose(const float* __restrict__ conv_w) {
    int f = blockIdx.x;
    for (int i = threadIdx.x; i < PLENN * KSZ; i += 256) {
        int p = i >> 3, k = i & 7;
        g_Wt[p * 256 + f * 8 + k] = conv_w[f * PLENN * KSZ + i];
    }
}

// 4 proteins per block; dynamic smem 4*ADIM floats
__global__ void k_buildA4(const int* __restrict__ target) {
    extern __shared__ float sA[];
    int tid = threadIdx.x;
    int b0 = blockIdx.x * 4;
    for (int i = tid; i < 4 * ADIM; i += 256) sA[i] = 0.f;
    __syncthreads();
    const int* t0 = target + (b0 + 0) * PLENN;
    const int* t1 = target + (b0 + 1) * PLENN;
    const int* t2 = target + (b0 + 2) * PLENN;
    const int* t3 = target + (b0 + 3) * PLENN;
    for (int p = 0; p < PLENN; p++) {
        float w = g_Wt[p * 256 + tid];
        sA[0 * ADIM + t0[p] * 256 + tid] += w;
        sA[1 * ADIM + t1[p] * 256 + tid] += w;
        sA[2 * ADIM + t2[p] * 256 + tid] += w;
        sA[3 * ADIM + t3[p] * 256 + tid] += w;
    }
    __syncthreads();
    for (int j = 0; j < 4; j++)
        for (int i = tid; i < ADIM; i += 256)
            g_A[(b0 + j) * ADIM + i] = sA[j * ADIM + i];
}

// U[(v*256+f*8+k)*128+o] = sum_t emb[v*128+t+k] * w_fcxt[(f*121+t)*128+o]
// grid (NFIL, VOCAB), 128 threads (o). Sliding window on emb row in smem.
__global__ void k_buildU(const float* __restrict__ emb, const float* __restrict__ wfcxt) {
    __shared__ float se[EMBD];
    int f = blockIdx.x, v = blockIdx.y, o = threadIdx.x;
    se[o] = emb[v * EMBD + o];
    __syncthreads();
    float acc[KSZ];
#pragma unroll
    for (int k = 0; k < KSZ; k++) acc[k] = 0.f;
    const float* wf = wfcxt + f * CLENN * OUTDIM + o;
#pragma unroll 4
    for (int t = 0; t < CLENN; t++) {
        float wv = wf[t * OUTDIM];
#pragma unroll
        for (int k = 0; k < KSZ; k++) acc[k] += se[t + k] * wv;
    }
#pragma unroll
    for (int k = 0; k < KSZ; k++)
        g_U[(v * 256 + f * 8 + k) * OUTDIM + o] = acc[k];
}

__global__ void k_bias2(const float* __restrict__ wfcxt, const float* __restrict__ conv_b) {
    int f = blockIdx.x, o = threadIdx.x; // 128 threads
    float s = 0.f;
    for (int t = 0; t < CLENN; t++) s += wfcxt[(f * CLENN + t) * OUTDIM + o];
    atomicAdd(&g_bias2[o], s * conv_b[f]);
}

__global__ void k_xtinit(const float* __restrict__ b_fcxt) {
    g_xc[blockIdx.x * 256 + 128 + threadIdx.x] = g_bias2[threadIdx.x] + b_fcxt[threadIdx.x];
}

__global__ void k_f2init(const float* __restrict__ b_fc2) {
    g_f2[blockIdx.x * 256 + threadIdx.x] = b_fc2[threadIdx.x];
}

// ---------------- GIN layers ----------------
// layer 1 projection: p = x @ w1a   (x: [N,78], w1a: [78,32])
__global__ void k_proj78(const float* __restrict__ x, const float* __restrict__ W) {
    __shared__ float xs[64][80];
    __shared__ float ws[78][33];
    int tid = threadIdx.x;
    int row0 = blockIdx.x * 64;
    const float* xb = x + row0 * FXDIM;
    for (int i = tid; i < 64 * FXDIM; i += 256) xs[i / FXDIM][i % FXDIM] = xb[i];
    for (int i = tid; i < FXDIM * 32; i += 256) ws[i >> 5][i & 31] = W[i];
    __syncthreads();
    int c = tid & 31, w = tid >> 5;
    float acc[8];
#pragma unroll
    for (int j = 0; j < 8; j++) acc[j] = 0.f;
    for (int k = 0; k < FXDIM; k++) {
        float wv = ws[k][c];
#pragma unroll
        for (int j = 0; j < 8; j++) acc[j] += xs[w * 8 + j][k] * wv;
    }
#pragma unroll
    for (int j = 0; j < 8; j++) g_p[(row0 + w * 8 + j) * 32 + c] = acc[j];
}

// layers 2-5 projection with folded BN affine: p = (y*s+t) @ W
__global__ void k_proj32(const float* __restrict__ W) {
    __shared__ float xs[64][33];
    __shared__ float ws[32][33];
    __shared__ float sa[64];
    int tid = threadIdx.x;
    int row0 = blockIdx.x * 64;
    if (tid < 64) sa[tid] = g_sb[tid];
    __syncthreads();
    for (int i = tid; i < 2048; i += 256) {
        int r = i >> 5, k = i & 31;
        xs[r][k] = g_y[(row0 + r) * 32 + k] * sa[k] + sa[32 + k];
    }
    for (int i = tid; i < 1024; i += 256) ws[i >> 5][i & 31] = W[i];
    __syncthreads();
    int c = tid & 31, w = tid >> 5;
    float acc[8];
#pragma unroll
    for (int j = 0; j < 8; j++) acc[j] = 0.f;
#pragma unroll
    for (int k = 0; k < 32; k++) {
        float wv = ws[k][c];
#pragma unroll
        for (int j = 0; j < 8; j++) acc[j] += xs[w * 8 + j][k] * wv;
    }
#pragma unroll
    for (int j = 0; j < 8; j++) g_p[(row0 + w * 8 + j) * 32 + c] = acc[j];
}

// fused: CSR gather-aggregate + relu(agg+ba) @ Wb + bb, relu, BN stat accumulation
__global__ void k_mlp(const float* __restrict__ ba, const float* __restrict__ Wb,
                      const float* __restrict__ bb) {
    __shared__ float us[64][33];
    __shared__ float ws[32][33];
    __shared__ float r1[8][32];
    __shared__ float r2[8][32];
    __shared__ float bsh[32], bbsh[32];
    int tid = threadIdx.x;
    int lane = tid & 31, wid = tid >> 5;
    int row0 = blockIdx.x * 64;
    if (tid < 32) { bsh[tid] = ba[tid]; bbsh[tid] = bb[tid]; }
    for (int i = tid; i < 1024; i += 256) ws[i >> 5][i & 31] = Wb[i];
    __syncthreads();
    // warp-per-node CSR aggregation directly into smem tile
#pragma unroll
    for (int nn = wid; nn < 64; nn += 8) {
        int node = row0 + nn;
        float acc = g_p[node * 32 + lane];
        int i = g_off[node], b1 = g_off[node + 1];
        for (; i + 4 <= b1; i += 4) {
            int s0 = g_srcl[i], s1 = g_srcl[i + 1], s2 = g_srcl[i + 2], s3 = g_srcl[i + 3];
            float a0 = g_p[s0 * 32 + lane];
            float a1 = g_p[s1 * 32 + lane];
            float a2 = g_p[s2 * 32 + lane];
            float a3 = g_p[s3 * 32 + lane];
            acc += (a0 + a1) + (a2 + a3);
        }
        for (; i < b1; i++) acc += g_p[g_srcl[i] * 32 + lane];
        us[nn][lane] = fmaxf(acc + bsh[lane], 0.f);
    }
    __syncthreads();
    int c = lane, w = wid;
    float acc[8];
#pragma unroll
    for (int j = 0; j < 8; j++) acc[j] = bbsh[c];
#pragma unroll
    for (int k = 0; k < 32; k++) {
        float wv = ws[k][c];
#pragma unroll
        for (int j = 0; j < 8; j++) acc[j] += us[w * 8 + j][k] * wv;
    }
    float s1 = 0.f, s2 = 0.f;
#pragma unroll
    for (int j = 0; j < 8; j++) {
        float v = fmaxf(acc[j], 0.f);
        g_y[(row0 + w * 8 + j) * 32 + c] = v;
        s1 += v;
        s2 += v * v;
    }
    r1[w][c] = s1;
    r2[w][c] = s2;
    __syncthreads();
    if (w == 0) {
        float a = 0.f, b2 = 0.f;
#pragma unroll
        for (int q = 0; q < 8; q++) { a += r1[q][c]; b2 += r2[q][c]; }
        atomicAdd(&g_stats[c], a);
        atomicAdd(&g_stats[32 + c], b2);
    }
}

// compute BN fold, then reset stats for the next layer (replay-safe)
__global__ void k_bnstats(const float* __restrict__ gamma, const float* __restrict__ beta) {
    int c = threadIdx.x; // 32 threads
    float m = g_stats[c] * (1.f / Nn);
    float v = g_stats[32 + c] * (1.f / Nn) - m * m;
    float s = gamma[c] * rsqrtf(v + 1e-5f);
    g_sb[c] = s;
    g_sb[32 + c] = beta[c] - m * s;
    g_stats[c] = 0.f;
    g_stats[32 + c] = 0.f;
}

// global add pool with BN affine applied on the fly
__global__ void k_pool(const int* __restrict__ batch) {
    int gid = blockIdx.x * 256 + threadIdx.x;
    int n = gid >> 5, d = gid & 31;
    if (n < Nn) {
        float v = g_y[n * 32 + d] * g_sb[d] + g_sb[32 + d];
        atomicAdd(&g_hg[batch[n] * 32 + d], v);
    }
}

// ---------------- generic fp32 GEMM: C[M,N] (+)= A[M,K] @ W[K,N] ----------------
template <bool RELU, bool ATOMIC>
__global__ void gemm64x128(const float* __restrict__ A, const float* __restrict__ W,
                           const float* __restrict__ bias, float* __restrict__ C,
                           int K, int ldc, int kChunk) {
    const int N = gridDim.y * 128;
    __shared__ float As[64][16];
    __shared__ float Ws[16][128];
    int tid = threadIdx.x;
    int tx = tid & 31, ty = tid >> 5;
    int row0 = blockIdx.x * 64;
    int col0 = blockIdx.y * 128;
    int k0 = blockIdx.z * kChunk;
    int k1 = k0 + kChunk;
    if (k1 > K) k1 = K;
    float acc[8][4];
#pragma unroll
    for (int i = 0; i < 8; i++)
#pragma unroll
        for (int m = 0; m < 4; m++) acc[i][m] = 0.f;
    int arow = tid >> 2, ak = (tid & 3) * 4;
    int wk = tid >> 4, wc = (tid & 15) * 8;
    for (int kb = k0; kb < k1; kb += 16) {
        float4 av = *(const float4*)(A + (row0 + arow) * K + kb + ak);
        *(float4*)(&As[arow][ak]) = av;
        float4 w0 = *(const float4*)(W + (kb + wk) * N + col0 + wc);
        float4 w1 = *(const float4*)(W + (kb + wk) * N + col0 + wc + 4);
        *(float4*)(&Ws[wk][wc]) = w0;
        *(float4*)(&Ws[wk][wc + 4]) = w1;
        __syncthreads();
#pragma unroll
        for (int kk = 0; kk < 16; kk++) {
            float rw[4];
#pragma unroll
            for (int m = 0; m < 4; m++) rw[m] = Ws[kk][tx + 32 * m];
#pragma unroll
            for (int i = 0; i < 8; i++) {
                float ra = As[ty * 8 + i][kk];
#pragma unroll
                for (int m = 0; m < 4; m++) acc[i][m] += ra * rw[m];
            }
        }
        __syncthreads();
    }
#pragma unroll
    for (int i = 0; i < 8; i++) {
        int r = row0 + ty * 8 + i;
#pragma unroll
        for (int m = 0; m < 4; m++) {
            int c = col0 + tx + 32 * m;
            if (ATOMIC) {
                atomicAdd(&C[r * ldc + c], acc[i][m]);
            } else {
                float v = acc[i][m] + (bias ? bias[c] : 0.f);
                if (RELU) v = fmaxf(v, 0.f);
                C[r * ldc + c] = v;
            }
        }
    }
}

// ---------------- final head ----------------
__global__ void k_out(const float* __restrict__ wout, const float* __restrict__ bout,
                      float* __restrict__ out) {
    int b = blockIdx.x, c = threadIdx.x; // 256 threads
    float v = fmaxf(g_f2[b * 256 + c], 0.f) * wout[c];
#pragma unroll
    for (int off = 16; off; off >>= 1) v += __shfl_down_sync(0xffffffffu, v, off);
    __shared__ float ps[8];
    if ((c & 31) == 0) ps[c >> 5] = v;
    __syncthreads();
    if (c == 0) {
        float t = bout[0];
#pragma unroll
        for (int q = 0; q < 8; q++) t += ps[q];
        out[b] = t;
    }
}

// ---------------- launcher ----------------
extern "C" void kernel_launch(void* const* d_in, const int* in_sizes, int n_in,
                              void* d_out, int out_size) {
    const float* x = (const float*)d_in[0];
    const int* edge_index = (const int*)d_in[1];
    const int* batch = (const int*)d_in[2];
    const int* target = (const int*)d_in[3];
    const float* w1a = (const float*)d_in[4];
    const float* b1a = (const float*)d_in[5];
    const float* w1b = (const float*)d_in[6];
    const float* b1b = (const float*)d_in[7];
    const float* wa = (const float*)d_in[8];
    const float* ba = (const float*)d_in[9];
    const float* wb = (const float*)d_in[10];
    const float* bb = (const float*)d_in[11];
    const float* gamma = (const float*)d_in[12];
    const float* beta = (const float*)d_in[13];
    const float* w_fcxd = (const float*)d_in[14];
    const float* b_fcxd = (const float*)d_in[15];
    const float* emb = (const float*)d_in[16];
    const float* conv_w = (const float*)d_in[17];
    const float* conv_b = (const float*)d_in[18];
    const float* w_fcxt = (const float*)d_in[19];
    const float* b_fcxt = (const float*)d_in[20];
    const float* w_fc1 = (const float*)d_in[21];
    const float* b_fc1 = (const float*)d_in[22];
    const float* w_fc2 = (const float*)d_in[23];
    const float* b_fc2 = (const float*)d_in[24];
    const float* w_out = (const float*)d_in[25];
    const float* b_out = (const float*)d_in[26];
    float* out = (float*)d_out;

    float *hgP, *xcP, *f1P, *f2P, *AP, *UP;
    cudaGetSymbolAddress((void**)&hgP, g_hg);
    cudaGetSymbolAddress((void**)&xcP, g_xc);
    cudaGetSymbolAddress((void**)&f1P, g_f1);
    cudaGetSymbolAddress((void**)&f2P, g_f2);
    cudaGetSymbolAddress((void**)&AP, g_A);
    cudaGetSymbolAddress((void**)&UP, g_U);

    cudaFuncSetAttribute(k_buildA4, cudaFuncAttributeMaxDynamicSharedMemorySize,
                         4 * ADIM * (int)sizeof(float));

    k_init<<<256, 256>>>();

    // CSR build
    k_hist<<<Ee / 256, 256>>>(edge_index);
    k_scan<<<1, 1024>>>();
    k_fill<<<Ee / 256, 256>>>(edge_index);

    // protein branch
    k_transpose<<<NFIL, 256>>>(conv_w);
    k_buildA4<<<Bb / 4, 256, 4 * ADIM * sizeof(float)>>>(target);
    k_buildU<<<dim3(NFIL, VOCAB), 128>>>(emb, w_fcxt);
    k_bias2<<<NFIL, 128>>>(w_fcxt, conv_b);
    k_xtinit<<<Bb, 128>>>(b_fcxt);
    k_f2init<<<Bb, 256>>>(b_fc2);

    // GIN layer 1
    k_proj78<<<Nn / 64, 256>>>(x, w1a);
    k_mlp<<<Nn / 64, 256>>>(b1a, w1b, b1b);
    k_bnstats<<<1, 32>>>(gamma, beta);

    // GIN layers 2-5
    for (int l = 0; l < 4; l++) {
        k_proj32<<<Nn / 64, 256>>>(wa + l * 1024);
        k_mlp<<<Nn / 64, 256>>>(ba + l * 32, wb + l * 1024, bb + l * 32);
        k_bnstats<<<1, 32>>>(gamma + (l + 1) * 32, beta + (l + 1) * 32);
    }

    // pool + drug head  (xd -> g_xc[:, 0:128])
    k_pool<<<(Nn * 32) / 256, 256>>>(batch);
    gemm64x128<true, false><<<dim3(16, 1, 1), 256>>>(hgP, w_fcxd, b_fcxd, xcP, 32, 256, 32);

    // protein head (xt -> g_xc[:, 128:256], atomic split-K onto bias-initialized region)
    gemm64x128<false, true><<<dim3(16, 1, 8), 256>>>(AP, UP, nullptr, xcP + 128, ADIM, 256, 832);

    // joint head
    gemm64x128<true, false><<<dim3(16, 8, 1), 256>>>(xcP, w_fc1, b_fc1, f1P, 256, 1024, 256);
    gemm64x128<false, true><<<dim3(16, 2, 4), 256>>>(f1P, w_fc2, nullptr, f2P, 1024, 256, 256);
    k_out<<<Bb, 256>>>(w_out, b_out, out);
}

// round 3
// speedup vs baseline: 1.6248x; 1.0769x over previous
#include <cuda_runtime.h>

#define Nn 65536
#define Ee 2097152
#define Bb 1024
#define FXDIM 78
#define DIM 32
#define EMBD 128
#define VOCAB 26
#define PLENN 1000
#define KSZ 8
#define CLENN 121
#define NFIL 32
#define ADIM 6656   /* VOCAB * NFIL * KSZ */
#define A4 1664     /* ADIM/4 */
#define OUTDIM 128

// ---------------- scratch (device globals; no allocations) ----------------
__device__ __align__(16) float g_p[Nn * DIM];
__device__ __align__(16) float g_y[Nn * DIM];
__device__ float g_stats[5 * 64];
__device__ float g_hg[Bb * DIM];
__device__ __align__(16) float g_xc[Bb * 256];    // [xd | xt]
__device__ __align__(16) float g_f1[Bb * 1024];
__device__ float g_f2[Bb * 256];
__device__ __align__(16) float g_Wt[PLENN * 256]; // conv_w transposed to [p][f*8+k]
__device__ __align__(16) float g_A[Bb * ADIM];
__device__ __align__(16) float g_U[ADIM * OUTDIM];
__device__ float g_bias2[OUTDIM];
// CSR scratch
__device__ int g_off[Nn + 1];
__device__ int g_pos[Nn];
__device__ int g_srcl[Ee];

__device__ __forceinline__ void f4add(float4& a, const float4& b) {
    a.x += b.x; a.y += b.y; a.z += b.z; a.w += b.w;
}

// ---------------- init ----------------
__global__ void k_init() {
    int i = blockIdx.x * 256 + threadIdx.x;   // 65536 threads
    if (i < Nn) g_pos[i] = 0;
    if (i < Bb * DIM) g_hg[i] = 0.f;
    if (i < 5 * 64) g_stats[i] = 0.f;
    if (i < OUTDIM) g_bias2[i] = 0.f;
}

// ---------------- CSR build ----------------
__global__ void k_hist(const int* __restrict__ ei) {
    int e = blockIdx.x * 256 + threadIdx.x;
    atomicAdd(&g_pos[ei[Ee + e]], 1);
}

__global__ void k_scan() {  // 1 block, 1024 threads, 64 elems each
    int t = threadIdx.x, lane = t & 31, wid = t >> 5;
    __shared__ int ws[32];
    int base = t * 64;
    int s = 0;
    for (int j = 0; j < 64; j++) s += g_pos[base + j];
    int v = s;
#pragma unroll
    for (int off = 1; off < 32; off <<= 1) {
        int u = __shfl_up_sync(0xffffffffu, v, off);
        if (lane >= off) v += u;
    }
    if (lane == 31) ws[wid] = v;
    __syncthreads();
    if (wid == 0) {
        int w = ws[lane];
#pragma unroll
        for (int off = 1; off < 32; off <<= 1) {
            int u = __shfl_up_sync(0xffffffffu, w, off);
            if (lane >= off) w += u;
        }
        ws[lane] = w;
    }
    __syncthreads();
    int run = v - s + (wid ? ws[wid - 1] : 0);
    for (int j = 0; j < 64; j++) {
        int d = g_pos[base + j];
        g_off[base + j] = run;
        g_pos[base + j] = run;
        run += d;
    }
    if (t == 1023) g_off[Nn] = run;
}

__global__ void k_fill(const int* __restrict__ ei) {
    int e = blockIdx.x * 256 + threadIdx.x;
    int d = ei[Ee + e];
    int slot = atomicAdd(&g_pos[d], 1);
    g_srcl[slot] = ei[e];
}

// ---------------- protein branch ----------------
__global__ void k_transpose(const float* __restrict__ conv_w) {
    int f = blockIdx.x;
    for (int i = threadIdx.x; i < PLENN * KSZ; i += 256) {
        int p = i >> 3, k = i & 7;
        g_Wt[p * 256 + f * 8 + k] = conv_w[f * PLENN * KSZ + i];
    }
}

// 4 proteins per block; 64 threads per protein, float4 smem RMW
__global__ void k_buildA4(const int* __restrict__ target) {
    extern __shared__ float4 sA4[];
    int tid = threadIdx.x;
    int b0 = blockIdx.x * 4;
    int pg = tid >> 6;          // protein slot 0..3
    int col4 = tid & 63;        // float4 column
    for (int i = tid; i < 4 * A4; i += 256) sA4[i] = make_float4(0.f, 0.f, 0.f, 0.f);
    __syncthreads();
    const float4* Wt4 = (const float4*)g_Wt;
    const int* tp = target + (b0 + pg) * PLENN;
    int pbase = pg * A4;
    for (int p = 0; p < PLENN; p += 2) {
        int va = tp[p], vb = tp[p + 1];
        float4 w0 = Wt4[p * 64 + col4];
        float4 w1 = Wt4[(p + 1) * 64 + col4];
        int ia = pbase + va * 64 + col4;
        float4 Aa = sA4[ia]; f4add(Aa, w0); sA4[ia] = Aa;
        int ib = pbase + vb * 64 + col4;
        float4 Ab = sA4[ib]; f4add(Ab, w1); sA4[ib] = Ab;
    }
    __syncthreads();
    float4* gA4 = (float4*)g_A;
    for (int j = 0; j < 4; j++)
        for (int i = tid; i < A4; i += 256)
            gA4[(b0 + j) * A4 + i] = sA4[j * A4 + i];
}

// U[(v*256+f*8+k)*128+o] = sum_t emb[v*128+t+k] * w_fcxt[(f*121+t)*128+o]
__global__ void k_buildU(const float* __restrict__ emb, const float* __restrict__ wfcxt) {
    __shared__ float se[EMBD];
    int f = blockIdx.x, v = blockIdx.y, o = threadIdx.x;
    se[o] = emb[v * EMBD + o];
    __syncthreads();
    float acc[KSZ];
#pragma unroll
    for (int k = 0; k < KSZ; k++) acc[k] = 0.f;
    const float* wf = wfcxt + f * CLENN * OUTDIM + o;
#pragma unroll 4
    for (int t = 0; t < CLENN; t++) {
        float wv = wf[t * OUTDIM];
#pragma unroll
        for (int k = 0; k < KSZ; k++) acc[k] += se[t + k] * wv;
    }
#pragma unroll
    for (int k = 0; k < KSZ; k++)
        g_U[(v * 256 + f * 8 + k) * OUTDIM + o] = acc[k];
}

__global__ void k_bias2(const float* __restrict__ wfcxt, const float* __restrict__ conv_b) {
    int f = blockIdx.x, o = threadIdx.x; // 128 threads
    float s = 0.f;
    for (int t = 0; t < CLENN; t++) s += wfcxt[(f * CLENN + t) * OUTDIM + o];
    atomicAdd(&g_bias2[o], s * conv_b[f]);
}

__global__ void k_xtinit(const float* __restrict__ b_fcxt) {
    g_xc[blockIdx.x * 256 + 128 + threadIdx.x] = g_bias2[threadIdx.x] + b_fcxt[threadIdx.x];
}

__global__ void k_f2init(const float* __restrict__ b_fc2) {
    g_f2[blockIdx.x * 256 + threadIdx.x] = b_fc2[threadIdx.x];
}

// ---------------- GIN layers ----------------
__global__ void k_proj78(const float* __restrict__ x, const float* __restrict__ W) {
    __shared__ float xs[64][80];
    __shared__ float ws[78][33];
    int tid = threadIdx.x;
    int row0 = blockIdx.x * 64;
    const float* xb = x + row0 * FXDIM;
    for (int i = tid; i < 64 * FXDIM; i += 256) xs[i / FXDIM][i % FXDIM] = xb[i];
    for (int i = tid; i < FXDIM * 32; i += 256) ws[i >> 5][i & 31] = W[i];
    __syncthreads();
    int c = tid & 31, w = tid >> 5;
    float acc[8];
#pragma unroll
    for (int j = 0; j < 8; j++) acc[j] = 0.f;
    for (int k = 0; k < FXDIM; k++) {
        float wv = ws[k][c];
#pragma unroll
        for (int j = 0; j < 8; j++) acc[j] += xs[w * 8 + j][k] * wv;
    }
#pragma unroll
    for (int j = 0; j < 8; j++) g_p[(row0 + w * 8 + j) * 32 + c] = acc[j];
}

// p = (y * s + t) @ W ; BN fold computed inline from stats slot
__global__ void k_proj32(int slot, const float* __restrict__ gamma,
                         const float* __restrict__ beta, const float* __restrict__ W) {
    __shared__ float xs[64][33];
    __shared__ float ws[32][33];
    __shared__ float sa[64];
    int tid = threadIdx.x;
    int row0 = blockIdx.x * 64;
    if (tid < 32) {
        float m = g_stats[slot * 64 + tid] * (1.f / Nn);
        float v = g_stats[slot * 64 + 32 + tid] * (1.f / Nn) - m * m;
        float s = gamma[tid] * rsqrtf(v + 1e-5f);
        sa[tid] = s;
        sa[32 + tid] = beta[tid] - m * s;
    }
    __syncthreads();
    const float4* y4 = (const float4*)g_y;
    for (int i = tid; i < 512; i += 256) {
        int r = i >> 3, q = i & 7;
        float4 v = y4[(row0 + r) * 8 + q];
        xs[r][q * 4 + 0] = v.x * sa[q * 4 + 0] + sa[32 + q * 4 + 0];
        xs[r][q * 4 + 1] = v.y * sa[q * 4 + 1] + sa[32 + q * 4 + 1];
        xs[r][q * 4 + 2] = v.z * sa[q * 4 + 2] + sa[32 + q * 4 + 2];
        xs[r][q * 4 + 3] = v.w * sa[q * 4 + 3] + sa[32 + q * 4 + 3];
    }
    for (int i = tid; i < 1024; i += 256) ws[i >> 5][i & 31] = W[i];
    __syncthreads();
    int c = tid & 31, w = tid >> 5;
    float acc[8];
#pragma unroll
    for (int j = 0; j < 8; j++) acc[j] = 0.f;
#pragma unroll
    for (int k = 0; k < 32; k++) {
        float wv = ws[k][c];
#pragma unroll
        for (int j = 0; j < 8; j++) acc[j] += xs[w * 8 + j][k] * wv;
    }
#pragma unroll
    for (int j = 0; j < 8; j++) g_p[(row0 + w * 8 + j) * 32 + c] = acc[j];
}

// fused: float4 CSR gather-aggregate (4 edges/warp-instr) + MLP + ReLU + BN stats
__global__ void k_mlp(int layer, const float* __restrict__ ba, const float* __restrict__ Wb,
                      const float* __restrict__ bb) {
    __shared__ float us[64][33];
    __shared__ float ws[32][33];
    __shared__ float r1[8][32];
    __shared__ float r2[8][32];
    __shared__ float bsh[32], bbsh[32];
    int tid = threadIdx.x;
    int lane = tid & 31, wid = tid >> 5;
    int row0 = blockIdx.x * 64;
    if (tid < 32) { bsh[tid] = ba[tid]; bbsh[tid] = bb[tid]; }
    for (int i = tid; i < 1024; i += 256) ws[i >> 5][i & 31] = Wb[i];
    __syncthreads();
    const float4* p4 = (const float4*)g_p;
    int eg = lane >> 3;   // edge slot 0..3
    int q = lane & 7;     // float4 chunk
    for (int nn = wid; nn < 64; nn += 8) {
        int node = row0 + nn;
        float4 a0 = make_float4(0.f, 0.f, 0.f, 0.f);
        float4 a1 = a0;
        if (eg == 0) a0 = p4[node * 8 + q];  // self term
        int i = g_off[node], i1 = g_off[node + 1];
        for (; i + 8 <= i1; i += 8) {
            int s0 = g_srcl[i + eg];
            int s1 = g_srcl[i + 4 + eg];
            float4 v0 = p4[s0 * 8 + q];
            float4 v1 = p4[s1 * 8 + q];
            f4add(a0, v0);
            f4add(a1, v1);
        }
        if (i + 4 <= i1) {
            int s = g_srcl[i + eg];
            float4 v = p4[s * 8 + q];
            f4add(a0, v);
            i += 4;
        }
        int rem = i1 - i;
        if (eg < rem) {
            int s = g_srcl[i + eg];
            float4 v = p4[s * 8 + q];
            f4add(a1, v);
        }
        f4add(a0, a1);
#pragma unroll
        for (int off = 8; off <= 16; off <<= 1) {
            a0.x += __shfl_xor_sync(0xffffffffu, a0.x, off);
            a0.y += __shfl_xor_sync(0xffffffffu, a0.y, off);
            a0.z += __shfl_xor_sync(0xffffffffu, a0.z, off);
            a0.w += __shfl_xor_sync(0xffffffffu, a0.w, off);
        }
        if (eg == 0) {
            us[nn][q * 4 + 0] = fmaxf(a0.x + bsh[q * 4 + 0], 0.f);
            us[nn][q * 4 + 1] = fmaxf(a0.y + bsh[q * 4 + 1], 0.f);
            us[nn][q * 4 + 2] = fmaxf(a0.z + bsh[q * 4 + 2], 0.f);
            us[nn][q * 4 + 3] = fmaxf(a0.w + bsh[q * 4 + 3], 0.f);
        }
    }
    __syncthreads();
    int c = lane, w = wid;
    float acc[8];
#pragma unroll
    for (int j = 0; j < 8; j++) acc[j] = bbsh[c];
#pragma unroll
    for (int k = 0; k < 32; k++) {
        float wv = ws[k][c];
#pragma unroll
        for (int j = 0; j < 8; j++) acc[j] += us[w * 8 + j][k] * wv;
    }
    float s1 = 0.f, s2 = 0.f;
#pragma unroll
    for (int j = 0; j < 8; j++) {
        float v = fmaxf(acc[j], 0.f);
        g_y[(row0 + w * 8 + j) * 32 + c] = v;
        s1 += v;
        s2 += v * v;
    }
    r1[w][c] = s1;
    r2[w][c] = s2;
    __syncthreads();
    if (w == 0) {
        float a = 0.f, b2 = 0.f;
#pragma unroll
        for (int qq = 0; qq < 8; qq++) { a += r1[qq][c]; b2 += r2[qq][c]; }
        atomicAdd(&g_stats[layer * 64 + c], a);
        atomicAdd(&g_stats[layer * 64 + 32 + c], b2);
    }
}

// global add pool: run-length accumulation + float4 reads, BN fold inline (slot 4)
__global__ void k_pool(const int* __restrict__ batch, const float* __restrict__ gamma,
                       const float* __restrict__ beta) {
    int tid = threadIdx.x;
    int lane = tid & 31;
    int gwarp = blockIdx.x * 8 + (tid >> 5);
    int q = lane & 7, sub = lane >> 3;
    int base = gwarp * 32;
    float s[4], t[4];
#pragma unroll
    for (int c = 0; c < 4; c++) {
        int d = q * 4 + c;
        float m = g_stats[4 * 64 + d] * (1.f / Nn);
        float vv = g_stats[4 * 64 + 32 + d] * (1.f / Nn) - m * m;
        s[c] = gamma[d] * rsqrtf(vv + 1e-5f);
        t[c] = beta[d] - m * s[c];
    }
    const float4* y4 = (const float4*)g_y;
    float4 acc = make_float4(0.f, 0.f, 0.f, 0.f);
    int cur = batch[base + sub];
#pragma unroll 2
    for (int j = 0; j < 8; j++) {
        int node = base + j * 4 + sub;
        int b = batch[node];
        float4 v = y4[node * 8 + q];
        v.x = v.x * s[0] + t[0];
        v.y = v.y * s[1] + t[1];
        v.z = v.z * s[2] + t[2];
        v.w = v.w * s[3] + t[3];
        if (b != cur) {
            atomicAdd(&g_hg[cur * 32 + q * 4 + 0], acc.x);
            atomicAdd(&g_hg[cur * 32 + q * 4 + 1], acc.y);
            atomicAdd(&g_hg[cur * 32 + q * 4 + 2], acc.z);
            atomicAdd(&g_hg[cur * 32 + q * 4 + 3], acc.w);
            acc = make_float4(0.f, 0.f, 0.f, 0.f);
            cur = b;
        }
        f4add(acc, v);
    }
    atomicAdd(&g_hg[cur * 32 + q * 4 + 0], acc.x);
    atomicAdd(&g_hg[cur * 32 + q * 4 + 1], acc.y);
    atomicAdd(&g_hg[cur * 32 + q * 4 + 2], acc.z);
    atomicAdd(&g_hg[cur * 32 + q * 4 + 3], acc.w);
}

// ---------------- generic fp32 GEMM: C[M,N] (+)= A[M,K] @ W[K,N] ----------------
template <bool RELU, bool ATOMIC>
__global__ void gemm64x128(const float* __restrict__ A, const float* __restrict__ W,
                           const float* __restrict__ bias, float* __restrict__ C,
                           int K, int ldc, int kChunk) {
    const int N = gridDim.y * 128;
    __shared__ float As[64][16];
    __shared__ float Ws[16][128];
    int tid = threadIdx.x;
    int tx = tid & 31, ty = tid >> 5;
    int row0 = blockIdx.x * 64;
    int col0 = blockIdx.y * 128;
    int k0 = blockIdx.z * kChunk;
    int k1 = k0 + kChunk;
    if (k1 > K) k1 = K;
    float acc[8][4];
#pragma unroll
    for (int i = 0; i < 8; i++)
#pragma unroll
        for (int m = 0; m < 4; m++) acc[i][m] = 0.f;
    int arow = tid >> 2, ak = (tid & 3) * 4;
    int wk = tid >> 4, wc = (tid & 15) * 8;
    for (int kb = k0; kb < k1; kb += 16) {
        float4 av = *(const float4*)(A + (row0 + arow) * K + kb + ak);
        *(float4*)(&As[arow][ak]) = av;
        float4 w0 = *(const float4*)(W + (kb + wk) * N + col0 + wc);
        float4 w1 = *(const float4*)(W + (kb + wk) * N + col0 + wc + 4);
        *(float4*)(&Ws[wk][wc]) = w0;
        *(float4*)(&Ws[wk][wc + 4]) = w1;
        __syncthreads();
#pragma unroll
        for (int kk = 0; kk < 16; kk++) {
            float rw[4];
#pragma unroll
            for (int m = 0; m < 4; m++) rw[m] = Ws[kk][tx + 32 * m];
#pragma unroll
            for (int i = 0; i < 8; i++) {
                float ra = As[ty * 8 + i][kk];
#pragma unroll
                for (int m = 0; m < 4; m++) acc[i][m] += ra * rw[m];
            }
        }
        __syncthreads();
    }
#pragma unroll
    for (int i = 0; i < 8; i++) {
        int r = row0 + ty * 8 + i;
#pragma unroll
        for (int m = 0; m < 4; m++) {
            int c = col0 + tx + 32 * m;
            if (ATOMIC) {
                atomicAdd(&C[r * ldc + c], acc[i][m]);
            } else {
                float v = acc[i][m] + (bias ? bias[c] : 0.f);
                if (RELU) v = fmaxf(v, 0.f);
                C[r * ldc + c] = v;
            }
        }
    }
}

// ---------------- final head ----------------
__global__ void k_out(const float* __restrict__ wout, const float* __restrict__ bout,
                      float* __restrict__ out) {
    int b = blockIdx.x, c = threadIdx.x; // 256 threads
    float v = fmaxf(g_f2[b * 256 + c], 0.f) * wout[c];
#pragma unroll
    for (int off = 16; off; off >>= 1) v += __shfl_down_sync(0xffffffffu, v, off);
    __shared__ float ps[8];
    if ((c & 31) == 0) ps[c >> 5] = v;
    __syncthreads();
    if (c == 0) {
        float t = bout[0];
#pragma unroll
        for (int q = 0; q < 8; q++) t += ps[q];
        out[b] = t;
    }
}

// ---------------- launcher ----------------
extern "C" void kernel_launch(void* const* d_in, const int* in_sizes, int n_in,
                              void* d_out, int out_size) {
    const float* x = (const float*)d_in[0];
    const int* edge_index = (const int*)d_in[1];
    const int* batch = (const int*)d_in[2];
    const int* target = (const int*)d_in[3];
    const float* w1a = (const float*)d_in[4];
    const float* b1a = (const float*)d_in[5];
    const float* w1b = (const float*)d_in[6];
    const float* b1b = (const float*)d_in[7];
    const float* wa = (const float*)d_in[8];
    const float* ba = (const float*)d_in[9];
    const float* wb = (const float*)d_in[10];
    const float* bb = (const float*)d_in[11];
    const float* gamma = (const float*)d_in[12];
    const float* beta = (const float*)d_in[13];
    const float* w_fcxd = (const float*)d_in[14];
    const float* b_fcxd = (const float*)d_in[15];
    const float* emb = (const float*)d_in[16];
    const float* conv_w = (const float*)d_in[17];
    const float* conv_b = (const float*)d_in[18];
    const float* w_fcxt = (const float*)d_in[19];
    const float* b_fcxt = (const float*)d_in[20];
    const float* w_fc1 = (const float*)d_in[21];
    const float* b_fc1 = (const float*)d_in[22];
    const float* w_fc2 = (const float*)d_in[23];
    const float* b_fc2 = (const float*)d_in[24];
    const float* w_out = (const float*)d_in[25];
    const float* b_out = (const float*)d_in[26];
    float* out = (float*)d_out;

    float *hgP, *xcP, *f1P, *f2P, *AP, *UP;
    cudaGetSymbolAddress((void**)&hgP, g_hg);
    cudaGetSymbolAddress((void**)&xcP, g_xc);
    cudaGetSymbolAddress((void**)&f1P, g_f1);
    cudaGetSymbolAddress((void**)&f2P, g_f2);
    cudaGetSymbolAddress((void**)&AP, g_A);
    cudaGetSymbolAddress((void**)&UP, g_U);

    cudaFuncSetAttribute(k_buildA4, cudaFuncAttributeMaxDynamicSharedMemorySize,
                         4 * ADIM * (int)sizeof(float));

    k_init<<<256, 256>>>();

    // CSR build
    k_hist<<<Ee / 256, 256>>>(edge_index);
    k_scan<<<1, 1024>>>();
    k_fill<<<Ee / 256, 256>>>(edge_index);

    // protein branch
    k_transpose<<<NFIL, 256>>>(conv_w);
    k_buildA4<<<Bb / 4, 256, 4 * ADIM * sizeof(float)>>>(target);
    k_buildU<<<dim3(NFIL, VOCAB), 128>>>(emb, w_fcxt);
    k_bias2<<<NFIL, 128>>>(w_fcxt, conv_b);
    k_xtinit<<<Bb, 128>>>(b_fcxt);
    k_f2init<<<Bb, 256>>>(b_fc2);

    // GIN layer 1
    k_proj78<<<Nn / 64, 256>>>(x, w1a);
    k_mlp<<<Nn / 64, 256>>>(0, b1a, w1b, b1b);

    // GIN layers 2-5
    for (int l = 0; l < 4; l++) {
        k_proj32<<<Nn / 64, 256>>>(l, gamma + l * 32, beta + l * 32, wa + l * 1024);
        k_mlp<<<Nn / 64, 256>>>(l + 1, ba + l * 32, wb + l * 1024, bb + l * 32);
    }

    // pool + drug head  (xd -> g_xc[:, 0:128])
    k_pool<<<Nn / 256, 256>>>(batch, gamma + 128, beta + 128);
    gemm64x128<true, false><<<dim3(16, 1, 1), 256>>>(hgP, w_fcxd, b_fcxd, xcP, 32, 256, 32);

    // protein head (xt -> g_xc[:, 128:256], atomic split-K onto bias-initialized region)
    gemm64x128<false, true><<<dim3(16, 1, 8), 256>>>(AP, UP, nullptr, xcP + 128, ADIM, 256, 832);

    // joint head
    gemm64x128<true, false><<<dim3(16, 8, 1), 256>>>(xcP, w_fc1, b_fc1, f1P, 256, 1024, 256);
    gemm64x128<false, true><<<dim3(16, 2, 4), 256>>>(f1P, w_fc2, nullptr, f2P, 1024, 256, 256);
    k_out<<<Bb, 256>>>(w_out, b_out, out);
}

// round 5
// speedup vs baseline: 2.3984x; 1.4761x over previous
#include <cuda_runtime.h>

#define Nn 65536
#define Ee 2097152
#define Bb 1024
#define FXDIM 78
#define DIM 32
#define EMBD 128
#define VOCAB 26
#define PLENN 1000
#define KSZ 8
#define CLENN 121
#define NFIL 32
#define ADIM 6656   /* VOCAB * NFIL * KSZ */
#define A4 1664     /* ADIM/4 */
#define OUTDIM 128

// ---------------- scratch (device globals; no allocations) ----------------
__device__ __align__(16) float g_p[Nn * DIM];
__device__ __align__(16) float g_y[Nn * DIM];
__device__ float g_stats[5 * 64];
__device__ float g_hg[Bb * DIM];
__device__ __align__(16) float g_xc[Bb * 256];    // [xd | xt]
__device__ __align__(16) float g_f1[Bb * 1024];
__device__ __align__(16) float g_f2[Bb * 256];
__device__ __align__(16) float g_Wt[PLENN * 256]; // conv_w transposed to [p][f*8+k]
__device__ __align__(16) float g_A[Bb * ADIM];
__device__ __align__(16) float g_U[ADIM * OUTDIM];
__device__ __align__(16) float g_bias2[OUTDIM];
__device__ __align__(16) float g_part[16 * 1024 * 128];   // split-K partials (8 MB)
// CSR scratch
__device__ __align__(16) int g_off[Nn + 4];
__device__ __align__(16) int g_pos[Nn];
__device__ __align__(16) int g_srcl[Ee];

__device__ __forceinline__ void f4add(float4& a, const float4& b) {
    a.x += b.x; a.y += b.y; a.z += b.z; a.w += b.w;
}

// ---------------- init ----------------
__global__ void k_init() {
    int i = blockIdx.x * 256 + threadIdx.x;   // 65536 threads
    if (i < Nn) g_pos[i] = 0;
    if (i < Bb * DIM) g_hg[i] = 0.f;
    if (i < 5 * 64) g_stats[i] = 0.f;
    if (i < OUTDIM) g_bias2[i] = 0.f;
}

// ---------------- CSR build (vectorized) ----------------
__global__ void k_hist(const int* __restrict__ ei) {
    int e4 = blockIdx.x * 256 + threadIdx.x;
    int4 d = ((const int4*)(ei + Ee))[e4];
    atomicAdd(&g_pos[d.x], 1);
    atomicAdd(&g_pos[d.y], 1);
    atomicAdd(&g_pos[d.z], 1);
    atomicAdd(&g_pos[d.w], 1);
}

__global__ void k_scan() {  // 1 block, 1024 threads, 64 elems each
    int t = threadIdx.x, lane = t & 31, wid = t >> 5;
    __shared__ int ws[32];
    const int4* pos4 = (const int4*)g_pos;
    int base4 = t * 16;
    int s = 0;
#pragma unroll
    for (int j = 0; j < 16; j++) {
        int4 v = pos4[base4 + j];
        s += v.x + v.y + v.z + v.w;
    }
    int v = s;
#pragma unroll
    for (int off = 1; off < 32; off <<= 1) {
        int u = __shfl_up_sync(0xffffffffu, v, off);
        if (lane >= off) v += u;
    }
    if (lane == 31) ws[wid] = v;
    __syncthreads();
    if (wid == 0) {
        int w = ws[lane];
#pragma unroll
        for (int off = 1; off < 32; off <<= 1) {
            int u = __shfl_up_sync(0xffffffffu, w, off);
            if (lane >= off) w += u;
        }
        ws[lane] = w;
    }
    __syncthreads();
    int run = v - s + (wid ? ws[wid - 1] : 0);
    int4* off4 = (int4*)g_off;
    int4* posw4 = (int4*)g_pos;
#pragma unroll
    for (int j = 0; j < 16; j++) {
        int4 d = pos4[base4 + j];
        int4 o;
        o.x = run;
        o.y = run + d.x;
        o.z = o.y + d.y;
        o.w = o.z + d.z;
        off4[base4 + j] = o;
        posw4[base4 + j] = o;
        run = o.w + d.w;
    }
    if (t == 1023) g_off[Nn] = run;
}

__global__ void k_fill(const int* __restrict__ ei) {
    int e4 = blockIdx.x * 256 + threadIdx.x;
    int4 sv = ((const int4*)ei)[e4];
    int4 dv = ((const int4*)(ei + Ee))[e4];
    int s0 = atomicAdd(&g_pos[dv.x], 1); g_srcl[s0] = sv.x;
    int s1 = atomicAdd(&g_pos[dv.y], 1); g_srcl[s1] = sv.y;
    int s2 = atomicAdd(&g_pos[dv.z], 1); g_srcl[s2] = sv.z;
    int s3 = atomicAdd(&g_pos[dv.w], 1); g_srcl[s3] = sv.w;
}

// ---------------- protein branch ----------------
__global__ void k_transpose(const float* __restrict__ conv_w) {
    int f = blockIdx.x;
    for (int i = threadIdx.x; i < PLENN * KSZ; i += 256) {
        int p = i >> 3, k = i & 7;
        g_Wt[p * 256 + f * 8 + k] = conv_w[f * PLENN * KSZ + i];
    }
}

// 4 proteins per block; 64 threads per protein, float4 smem RMW
__global__ void k_buildA4(const int* __restrict__ target) {
    extern __shared__ float4 sA4[];
    int tid = threadIdx.x;
    int b0 = blockIdx.x * 4;
    int pg = tid >> 6;          // protein slot 0..3
    int col4 = tid & 63;        // float4 column
    for (int i = tid; i < 4 * A4; i += 256) sA4[i] = make_float4(0.f, 0.f, 0.f, 0.f);
    __syncthreads();
    const float4* Wt4 = (const float4*)g_Wt;
    const int* tp = target + (b0 + pg) * PLENN;
    int pbase = pg * A4;
    for (int p = 0; p < PLENN; p += 2) {
        int va = tp[p], vb = tp[p + 1];
        float4 w0 = Wt4[p * 64 + col4];
        float4 w1 = Wt4[(p + 1) * 64 + col4];
        int ia = pbase + va * 64 + col4;
        float4 Aa = sA4[ia]; f4add(Aa, w0); sA4[ia] = Aa;
        int ib = pbase + vb * 64 + col4;
        float4 Ab = sA4[ib]; f4add(Ab, w1); sA4[ib] = Ab;
    }
    __syncthreads();
    float4* gA4 = (float4*)g_A;
    for (int j = 0; j < 4; j++)
        for (int i = tid; i < A4; i += 256)
            gA4[(b0 + j) * A4 + i] = sA4[j * A4 + i];
}

// U[(v*256+f*8+k)*128+o] = sum_t emb[v*128+t+k] * w_fcxt[(f*121+t)*128+o]
__global__ void k_buildU(const float* __restrict__ emb, const float* __restrict__ wfcxt) {
    __shared__ float se[EMBD];
    int f = blockIdx.x, v = blockIdx.y, o = threadIdx.x;
    se[o] = emb[v * EMBD + o];
    __syncthreads();
    float acc[KSZ];
#pragma unroll
    for (int k = 0; k < KSZ; k++) acc[k] = 0.f;
    const float* wf = wfcxt + f * CLENN * OUTDIM + o;
#pragma unroll 4
    for (int t = 0; t < CLENN; t++) {
        float wv = wf[t * OUTDIM];
#pragma unroll
        for (int k = 0; k < KSZ; k++) acc[k] += se[t + k] * wv;
    }
#pragma unroll
    for (int k = 0; k < KSZ; k++)
        g_U[(v * 256 + f * 8 + k) * OUTDIM + o] = acc[k];
}

__global__ void k_bias2(const float* __restrict__ wfcxt, const float* __restrict__ conv_b) {
    int f = blockIdx.x, o = threadIdx.x; // 128 threads
    float s = 0.f;
    for (int t = 0; t < CLENN; t++) s += wfcxt[(f * CLENN + t) * OUTDIM + o];
    atomicAdd(&g_bias2[o], s * conv_b[f]);
}

// ---------------- GIN layers ----------------
__global__ void k_proj78(const float* __restrict__ x, const float* __restrict__ W) {
    __shared__ float xs[64][80];
    __shared__ float ws[78][33];
    int tid = threadIdx.x;
    int row0 = blockIdx.x * 64;
    const float* xb = x + row0 * FXDIM;
    for (int i = tid; i < 64 * FXDIM; i += 256) xs[i / FXDIM][i % FXDIM] = xb[i];
    for (int i = tid; i < FXDIM * 32; i += 256) ws[i >> 5][i & 31] = W[i];
    __syncthreads();
    int c = tid & 31, w = tid >> 5;
    float acc[8];
#pragma unroll
    for (int j = 0; j < 8; j++) acc[j] = 0.f;
    for (int k = 0; k < FXDIM; k++) {
        float wv = ws[k][c];
#pragma unroll
        for (int j = 0; j < 8; j++) acc[j] += xs[w * 8 + j][k] * wv;
    }
#pragma unroll
    for (int j = 0; j < 8; j++) g_p[(row0 + w * 8 + j) * 32 + c] = acc[j];
}

// p = (y * s + t) @ W ; BN fold computed inline from stats slot
__global__ void k_proj32(int slot, const float* __restrict__ gamma,
                         const float* __restrict__ beta, const float* __restrict__ W) {
    __shared__ float xs[64][33];
    __shared__ float ws[32][33];
    __shared__ float sa[64];
    int tid = threadIdx.x;
    int row0 = blockIdx.x * 64;
    if (tid < 32) {
        float m = g_stats[slot * 64 + tid] * (1.f / Nn);
        float v = g_stats[slot * 64 + 32 + tid] * (1.f / Nn) - m * m;
        float s = gamma[tid] * rsqrtf(v + 1e-5f);
        sa[tid] = s;
        sa[32 + tid] = beta[tid] - m * s;
    }
    __syncthreads();
    const float4* y4 = (const float4*)g_y;
    for (int i = tid; i < 512; i += 256) {
        int r = i >> 3, q = i & 7;
        float4 v = y4[(row0 + r) * 8 + q];
        xs[r][q * 4 + 0] = v.x * sa[q * 4 + 0] + sa[32 + q * 4 + 0];
        xs[r][q * 4 + 1] = v.y * sa[q * 4 + 1] + sa[32 + q * 4 + 1];
        xs[r][q * 4 + 2] = v.z * sa[q * 4 + 2] + sa[32 + q * 4 + 2];
        xs[r][q * 4 + 3] = v.w * sa[q * 4 + 3] + sa[32 + q * 4 + 3];
    }
    for (int i = tid; i < 1024; i += 256) ws[i >> 5][i & 31] = W[i];
    __syncthreads();
    int c = tid & 31, w = tid >> 5;
    float acc[8];
#pragma unroll
    for (int j = 0; j < 8; j++) acc[j] = 0.f;
#pragma unroll
    for (int k = 0; k < 32; k++) {
        float wv = ws[k][c];
#pragma unroll
        for (int j = 0; j < 8; j++) acc[j] += xs[w * 8 + j][k] * wv;
    }
#pragma unroll
    for (int j = 0; j < 8; j++) g_p[(row0 + w * 8 + j) * 32 + c] = acc[j];
}

// fused: float4 CSR gather-aggregate (4 edges/warp-instr) + MLP + ReLU + BN stats
__global__ void k_mlp(int layer, const float* __restrict__ ba, const float* __restrict__ Wb,
                      const float* __restrict__ bb) {
    __shared__ float us[64][33];
    __shared__ float ws[32][33];
    __shared__ float r1[8][32];
    __shared__ float r2[8][32];
    __shared__ float bsh[32], bbsh[32];
    int tid = threadIdx.x;
    int lane = tid & 31, wid = tid >> 5;
    int row0 = blockIdx.x * 64;
    if (tid < 32) { bsh[tid] = ba[tid]; bbsh[tid] = bb[tid]; }
    for (int i = tid; i < 1024; i += 256) ws[i >> 5][i & 31] = Wb[i];
    __syncthreads();
    const float4* p4 = (const float4*)g_p;
    int eg = lane >> 3;   // edge slot 0..3
    int q = lane & 7;     // float4 chunk
    for (int nn = wid; nn < 64; nn += 8) {
        int node = row0 + nn;
        float4 a0 = make_float4(0.f, 0.f, 0.f, 0.f);
        float4 a1 = a0;
        if (eg == 0) a0 = p4[node * 8 + q];  // self term
        int i = g_off[node], i1 = g_off[node + 1];
        for (; i + 8 <= i1; i += 8) {
            int s0 = g_srcl[i + eg];
            int s1 = g_srcl[i + 4 + eg];
            float4 v0 = p4[s0 * 8 + q];
            float4 v1 = p4[s1 * 8 + q];
            f4add(a0, v0);
            f4add(a1, v1);
        }
        if (i + 4 <= i1) {
            int s = g_srcl[i + eg];
            float4 v = p4[s * 8 + q];
            f4add(a0, v);
            i += 4;
        }
        int rem = i1 - i;
        if (eg < rem) {
            int s = g_srcl[i + eg];
            float4 v = p4[s * 8 + q];
            f4add(a1, v);
        }
        f4add(a0, a1);
#pragma unroll
        for (int off = 8; off <= 16; off <<= 1) {
            a0.x += __shfl_xor_sync(0xffffffffu, a0.x, off);
            a0.y += __shfl_xor_sync(0xffffffffu, a0.y, off);
            a0.z += __shfl_xor_sync(0xffffffffu, a0.z, off);
            a0.w += __shfl_xor_sync(0xffffffffu, a0.w, off);
        }
        if (eg == 0) {
            us[nn][q * 4 + 0] = fmaxf(a0.x + bsh[q * 4 + 0], 0.f);
            us[nn][q * 4 + 1] = fmaxf(a0.y + bsh[q * 4 + 1], 0.f);
            us[nn][q * 4 + 2] = fmaxf(a0.z + bsh[q * 4 + 2], 0.f);
            us[nn][q * 4 + 3] = fmaxf(a0.w + bsh[q * 4 + 3], 0.f);
        }
    }
    __syncthreads();
    int c = lane, w = wid;
    float acc[8];
#pragma unroll
    for (int j = 0; j < 8; j++) acc[j] = bbsh[c];
#pragma unroll
    for (int k = 0; k < 32; k++) {
        float wv = ws[k][c];
#pragma unroll
        for (int j = 0; j < 8; j++) acc[j] += us[w * 8 + j][k] * wv;
    }
    float s1 = 0.f, s2 = 0.f;
#pragma unroll
    for (int j = 0; j < 8; j++) {
        float v = fmaxf(acc[j], 0.f);
        g_y[(row0 + w * 8 + j) * 32 + c] = v;
        s1 += v;
        s2 += v * v;
    }
    r1[w][c] = s1;
    r2[w][c] = s2;
    __syncthreads();
    if (w == 0) {
        float a = 0.f, b2 = 0.f;
#pragma unroll
        for (int qq = 0; qq < 8; qq++) { a += r1[qq][c]; b2 += r2[qq][c]; }
        atomicAdd(&g_stats[layer * 64 + c], a);
        atomicAdd(&g_stats[layer * 64 + 32 + c], b2);
    }
}

// global add pool: run-length accumulation + float4 reads, BN fold inline (slot 4)
__global__ void k_pool(const int* __restrict__ batch, const float* __restrict__ gamma,
                       const float* __restrict__ beta) {
    int tid = threadIdx.x;
    int lane = tid & 31;
    int gwarp = blockIdx.x * 8 + (tid >> 5);
    int q = lane & 7, sub = lane >> 3;
    int base = gwarp * 32;
    float s[4], t[4];
#pragma unroll
    for (int c = 0; c < 4; c++) {
        int d = q * 4 + c;
        float m = g_stats[4 * 64 + d] * (1.f / Nn);
        float vv = g_stats[4 * 64 + 32 + d] * (1.f / Nn) - m * m;
        s[c] = gamma[d] * rsqrtf(vv + 1e-5f);
        t[c] = beta[d] - m * s[c];
    }
    const float4* y4 = (const float4*)g_y;
    float4 acc = make_float4(0.f, 0.f, 0.f, 0.f);
    int cur = batch[base + sub];
#pragma unroll 2
    for (int j = 0; j < 8; j++) {
        int node = base + j * 4 + sub;
        int b = batch[node];
        float4 v = y4[node * 8 + q];
        v.x = v.x * s[0] + t[0];
        v.y = v.y * s[1] + t[1];
        v.z = v.z * s[2] + t[2];
        v.w = v.w * s[3] + t[3];
        if (b != cur) {
            atomicAdd(&g_hg[cur * 32 + q * 4 + 0], acc.x);
            atomicAdd(&g_hg[cur * 32 + q * 4 + 1], acc.y);
            atomicAdd(&g_hg[cur * 32 + q * 4 + 2], acc.z);
            atomicAdd(&g_hg[cur * 32 + q * 4 + 3], acc.w);
            acc = make_float4(0.f, 0.f, 0.f, 0.f);
            cur = b;
        }
        f4add(acc, v);
    }
    atomicAdd(&g_hg[cur * 32 + q * 4 + 0], acc.x);
    atomicAdd(&g_hg[cur * 32 + q * 4 + 1], acc.y);
    atomicAdd(&g_hg[cur * 32 + q * 4 + 2], acc.z);
    atomicAdd(&g_hg[cur * 32 + q * 4 + 3], acc.w);
}

// ---------------- high-efficiency SGEMM: BM=128, BK=16, 256 threads ----------------
// BN=128,TN=8  or  BN=64,TN=4.  PARTIAL: write split-K partials to g_part.
template <int BN, int TN, bool PARTIAL, bool RELU>
__global__ void gemm128(const float* __restrict__ A, const float* __restrict__ W,
                        const float* __restrict__ bias, float* __restrict__ C,
                        int K, int ldc, int kChunk, float* __restrict__ part) {
    const int N = gridDim.y * BN;
    __shared__ float As[16][132];
    __shared__ float Ws[16][BN];
    int tid = threadIdx.x;
    int tx = tid & 15, ty = tid >> 4;
    int row0 = blockIdx.x * 128;
    int col0 = blockIdx.y * BN;
    int k0 = blockIdx.z * kChunk;
    int k1 = k0 + kChunk;
    if (k1 > K) k1 = K;
    float acc[8][TN];
#pragma unroll
    for (int i = 0; i < 8; i++)
#pragma unroll
        for (int j = 0; j < TN; j++) acc[i][j] = 0.f;

    int ar = tid >> 2;               // 0..63
    int ak = (tid & 3) * 4;
    int wr = tid >> 4;               // 0..15
    int wc = (tid & 15) * (BN / 16); // 8 or 4

    for (int kb = k0; kb < k1; kb += 16) {
        const float* Ap = A + (row0 + ar) * K + kb + ak;
        float4 va = *(const float4*)Ap;
        float4 vb = *(const float4*)(Ap + 64 * K);
        As[ak + 0][ar] = va.x; As[ak + 1][ar] = va.y;
        As[ak + 2][ar] = va.z; As[ak + 3][ar] = va.w;
        As[ak + 0][ar + 64] = vb.x; As[ak + 1][ar + 64] = vb.y;
        As[ak + 2][ar + 64] = vb.z; As[ak + 3][ar + 64] = vb.w;
        const float* Wp = W + (kb + wr) * N + col0 + wc;
        if (BN == 128) {
            *(float4*)&Ws[wr][wc] = *(const float4*)Wp;
            *(float4*)&Ws[wr][wc + 4] = *(const float4*)(Wp + 4);
        } else {
            *(float4*)&Ws[wr][wc] = *(const float4*)Wp;
        }
        __syncthreads();
#pragma unroll
        for (int kk = 0; kk < 16; kk++) {
            float av[8], bv[TN];
            *(float4*)&av[0] = *(const float4*)&As[kk][ty * 8];
            *(float4*)&av[4] = *(const float4*)&As[kk][ty * 8 + 4];
            *(float4*)&bv[0] = *(const float4*)&Ws[kk][tx * 4];
            if (TN == 8) *(float4*)&bv[4] = *(const float4*)&Ws[kk][64 + tx * 4];
#pragma unroll
            for (int i = 0; i < 8; i++)
#pragma unroll
                for (int j = 0; j < TN; j++) acc[i][j] += av[i] * bv[j];
        }
        __syncthreads();
    }

    if (PARTIAL) {
        const int Mtot = gridDim.x * 128;
        float* P = part + (size_t)blockIdx.z * Mtot * N;
#pragma unroll
        for (int i = 0; i < 8; i++) {
            int r = row0 + ty * 8 + i;
            *(float4*)&P[r * N + col0 + tx * 4] = *(float4*)&acc[i][0];
            if (TN == 8)
                *(float4*)&P[r * N + col0 + 64 + tx * 4] = *(float4*)&acc[i][4];
        }
    } else {
#pragma unroll
        for (int i = 0; i < 8; i++) {
            int r = row0 + ty * 8 + i;
#pragma unroll
            for (int h = 0; h < TN / 4; h++) {
                int c = col0 + h * 64 + tx * 4;
                float4 v;
                v.x = acc[i][h * 4 + 0] + (bias ? bias[c + 0] : 0.f);
                v.y = acc[i][h * 4 + 1] + (bias ? bias[c + 1] : 0.f);
                v.z = acc[i][h * 4 + 2] + (bias ? bias[c + 2] : 0.f);
                v.w = acc[i][h * 4 + 3] + (bias ? bias[c + 3] : 0.f);
                if (RELU) {
                    v.x = fmaxf(v.x, 0.f); v.y = fmaxf(v.y, 0.f);
                    v.z = fmaxf(v.z, 0.f); v.w = fmaxf(v.w, 0.f);
                }
                *(float4*)&C[r * ldc + c] = v;
            }
        }
    }
}

// reduce xt partials (16 splits, 1024x128) into g_xc[:,128:256] with both biases
__global__ void k_reduce_xt(const float* __restrict__ b_fcxt) {
    int idx4 = blockIdx.x * 256 + threadIdx.x;   // 32768 float4s
    int i = idx4 * 4;
    int b = i >> 7, col = i & 127;
    const float4* P = (const float4*)g_part;
    float4 s = P[idx4];
#pragma unroll
    for (int k = 1; k < 16; k++) f4add(s, P[k * (Bb * 128 / 4) + idx4]);
    float4 bs = *(const float4*)&g_bias2[col];
    float4 bf = *(const float4*)&b_fcxt[col];
    s.x += bs.x + bf.x; s.y += bs.y + bf.y;
    s.z += bs.z + bf.z; s.w += bs.w + bf.w;
    *(float4*)&g_xc[b * 256 + 128 + col] = s;
}

// reduce fc2 partials (4 splits, 1024x256) into g_f2 with bias
__global__ void k_reduce_f2(const float* __restrict__ b_fc2) {
    int idx4 = blockIdx.x * 256 + threadIdx.x;   // 65536 float4s
    int i = idx4 * 4;
    int col = i & 255;
    const float4* P = (const float4*)g_part;
    float4 s = P[idx4];
#pragma unroll
    for (int k = 1; k < 4; k++) f4add(s, P[k * (Bb * 256 / 4) + idx4]);
    float4 bf = *(const float4*)&b_fc2[col];
    s.x += bf.x; s.y += bf.y; s.z += bf.z; s.w += bf.w;
    *(float4*)&g_f2[i] = s;
}

// ---------------- small GEMM for xd (M=1024,K=32,N=128) ----------------
__global__ void gemm_xd(const float* __restrict__ A, const float* __restrict__ W,
                        const float* __restrict__ bias, float* __restrict__ C) {
    __shared__ float As[64][33];
    __shared__ float Ws[32][128];
    int tid = threadIdx.x;
    int row0 = blockIdx.x * 64;
    for (int i = tid; i < 64 * 32; i += 256) As[i >> 5][i & 31] = A[row0 * 32 + i];
    for (int i = tid; i < 32 * 128; i += 256) Ws[i >> 7][i & 127] = W[i];
    __syncthreads();
    int tx = tid & 31, ty = tid >> 5;   // ty 0..7 -> 8 rows each, tx -> 4 cols
    float acc[8][4];
#pragma unroll
    for (int i = 0; i < 8; i++)
#pragma unroll
        for (int m = 0; m < 4; m++) acc[i][m] = 0.f;
#pragma unroll
    for (int k = 0; k < 32; k++) {
        float rw[4];
#pragma unroll
        for (int m = 0; m < 4; m++) rw[m] = Ws[k][tx + 32 * m];
#pragma unroll
        for (int i = 0; i < 8; i++) {
            float ra = As[ty * 8 + i][k];
#pragma unroll
            for (int m = 0; m < 4; m++) acc[i][m] += ra * rw[m];
        }
    }
#pragma unroll
    for (int i = 0; i < 8; i++) {
        int r = row0 + ty * 8 + i;
#pragma unroll
        for (int m = 0; m < 4; m++) {
            int c = tx + 32 * m;
            C[r * 256 + c] = fmaxf(acc[i][m] + bias[c], 0.f);
        }
    }
}

// ---------------- final head ----------------
__global__ void k_out(const float* __restrict__ wout, const float* __restrict__ bout,
                      float* __restrict__ out) {
    int b = blockIdx.x, c = threadIdx.x; // 256 threads
    float v = fmaxf(g_f2[b * 256 + c], 0.f) * wout[c];
#pragma unroll
    for (int off = 16; off; off >>= 1) v += __shfl_down_sync(0xffffffffu, v, off);
    __shared__ float ps[8];
    if ((c & 31) == 0) ps[c >> 5] = v;
    __syncthreads();
    if (c == 0) {
        float t = bout[0];
#pragma unroll
        for (int q = 0; q < 8; q++) t += ps[q];
        out[b] = t;
    }
}

// ---------------- launcher ----------------
extern "C" void kernel_launch(void* const* d_in, const int* in_sizes, int n_in,
                              void* d_out, int out_size) {
    const float* x = (const float*)d_in[0];
    const int* edge_index = (const int*)d_in[1];
    const int* batch = (const int*)d_in[2];
    const int* target = (const int*)d_in[3];
    const float* w1a = (const float*)d_in[4];
    const float* b1a = (const float*)d_in[5];
    const float* w1b = (const float*)d_in[6];
    const float* b1b = (const float*)d_in[7];
    const float* wa = (const float*)d_in[8];
    const float* ba = (const float*)d_in[9];
    const float* wb = (const float*)d_in[10];
    const float* bb = (const float*)d_in[11];
    const float* gamma = (const float*)d_in[12];
    const float* beta = (const float*)d_in[13];
    const float* w_fcxd = (const float*)d_in[14];
    const float* b_fcxd = (const float*)d_in[15];
    const float* emb = (const float*)d_in[16];
    const float* conv_w = (const float*)d_in[17];
    const float* conv_b = (const float*)d_in[18];
    const float* w_fcxt = (const float*)d_in[19];
    const float* b_fcxt = (const float*)d_in[20];
    const float* w_fc1 = (const float*)d_in[21];
    const float* b_fc1 = (const float*)d_in[22];
    const float* w_fc2 = (const float*)d_in[23];
    const float* b_fc2 = (const float*)d_in[24];
    const float* w_out = (const float*)d_in[25];
    const float* b_out = (const float*)d_in[26];
    float* out = (float*)d_out;

    float *hgP, *xcP, *f1P, *AP, *UP, *partP;
    cudaGetSymbolAddress((void**)&hgP, g_hg);
    cudaGetSymbolAddress((void**)&xcP, g_xc);
    cudaGetSymbolAddress((void**)&f1P, g_f1);
    cudaGetSymbolAddress((void**)&AP, g_A);
    cudaGetSymbolAddress((void**)&UP, g_U);
    cudaGetSymbolAddress((void**)&partP, g_part);

    cudaFuncSetAttribute(k_buildA4, cudaFuncAttributeMaxDynamicSharedMemorySize,
                         4 * ADIM * (int)sizeof(float));

    // one-time second stream for protein-branch overlap (fork-join capture pattern)
    static cudaStream_t s2 = 0;
    static cudaEvent_t evF = 0, evJ = 0;
    static bool tried = false;
    static bool use2 = false;
    if (!tried) {
        tried = true;
        if (cudaStreamCreateWithFlags(&s2, cudaStreamNonBlocking) == cudaSuccess &&
            cudaEventCreateWithFlags(&evF, cudaEventDisableTiming) == cudaSuccess &&
            cudaEventCreateWithFlags(&evJ, cudaEventDisableTiming) == cudaSuccess) {
            use2 = true;
        } else {
            s2 = 0;
        }
    }
    cudaStream_t st2 = use2 ? s2 : (cudaStream_t)0;

    k_init<<<256, 256>>>();

    if (use2) {
        cudaEventRecord(evF, 0);
        cudaStreamWaitEvent(st2, evF, 0);
    }

    // ---- stream 2: protein branch + xt GEMM ----
    k_transpose<<<NFIL, 256, 0, st2>>>(conv_w);
    k_buildA4<<<Bb / 4, 256, 4 * ADIM * sizeof(float), st2>>>(target);
    k_buildU<<<dim3(NFIL, VOCAB), 128, 0, st2>>>(emb, w_fcxt);
    k_bias2<<<NFIL, 128, 0, st2>>>(w_fcxt, conv_b);
    gemm128<128, 8, true, false><<<dim3(8, 1, 16), 256, 0, st2>>>(
        AP, UP, nullptr, nullptr, ADIM, 0, 416, partP);
    k_reduce_xt<<<128, 256, 0, st2>>>(b_fcxt);

    // ---- stream 0: CSR + GIN chain ----
    k_hist<<<Ee / 1024, 256>>>(edge_index);
    k_scan<<<1, 1024>>>();
    k_fill<<<Ee / 1024, 256>>>(edge_index);

    k_proj78<<<Nn / 64, 256>>>(x, w1a);
    k_mlp<<<Nn / 64, 256>>>(0, b1a, w1b, b1b);
    for (int l = 0; l < 4; l++) {
        k_proj32<<<Nn / 64, 256>>>(l, gamma + l * 32, beta + l * 32, wa + l * 1024);
        k_mlp<<<Nn / 64, 256>>>(l + 1, ba + l * 32, wb + l * 1024, bb + l * 32);
    }
    k_pool<<<Nn / 256, 256>>>(batch, gamma + 128, beta + 128);
    gemm_xd<<<16, 256>>>(hgP, w_fcxd, b_fcxd, xcP);

    if (use2) {
        cudaEventRecord(evJ, st2);
        cudaStreamWaitEvent(0, evJ, 0);
    }

    // ---- joint head ----
    gemm128<64, 4, false, true><<<dim3(8, 16, 1), 256>>>(
        xcP, w_fc1, b_fc1, f1P, 256, 1024, 256, nullptr);
    gemm128<64, 4, true, false><<<dim3(8, 4, 4), 256>>>(
        f1P, w_fc2, nullptr, nullptr, 1024, 0, 256, partP);
    k_reduce_f2<<<256, 256>>>(b_fc2);
    k_out<<<Bb, 256>>>(w_out, b_out, out);
}